// round 15
// baseline (speedup 1.0000x reference)
#include <cuda_runtime.h>
#include <cuda_bf16.h>

// KuramotoDaidoMeanField — closed-form evaluation (no iteration), FINAL.
// Consensus R8 arithmetic (rel_err canary 4.323573e-05), with the entry
// thread-guard removed (grid is exactly <<<1,1>>>) so the 6 MLP input loads
// issue at instruction 0. All other knobs measured neutral/harmful across
// R8-R14; dur sits at the harness single-launch floor (6.6-6.9 us band).
//
// Math (derived R5):
//   Euler map z' = (b - i c) z, b = b0 - g s, s = |z|^2
//   => s' = s*m(s); m(s)-1 = C (s - s_inf)(s - r2), s_inf = (b0-sqrt(1-c^2))/g.
// Phase over the full trajectory via Abel/Euler-Maclaurin:
//   Sum phi(s_j) = N*phi_inf + exact-partial-fraction rational integral
//                + (1/2)Int psi D'/D ds (3-pt Gauss) + psi(s0)/2.
// Magnitude: sqrt(s_inf) (rho^N -> 0 enforced by guard).
// FP64 only for n*phi_inf (rsqrtf seed + 1 double Newton) and the mod-2pi
// fold; everything else float with __fdividef/__logf. Non-conforming inputs
// take the exact full-iteration fallback.

#define DT 0.01f

__device__ __forceinline__ float atan_small_f(float y)
{
    const float y2 = y * y;
    float p = -1.0f / 7.0f;
    p = __fmaf_rn(p, y2,  1.0f / 5.0f);
    p = __fmaf_rn(p, y2, -1.0f / 3.0f);
    p = __fmaf_rn(p, y2,  1.0f);
    return y * p;
}

__device__ __forceinline__ float log1p_small_f(float x)
{
    float p =  1.0f / 5.0f;
    p = __fmaf_rn(p, x, -1.0f / 4.0f);
    p = __fmaf_rn(p, x,  1.0f / 3.0f);
    p = __fmaf_rn(p, x, -1.0f / 2.0f);
    return x * __fmaf_rn(p, x, 1.0f);
}

__global__ void kuramoto_kernel(const float* __restrict__ omega_mean,
                                const float* __restrict__ coupling,
                                const float* __restrict__ delta,
                                const float* __restrict__ Z_real,
                                const float* __restrict__ Z_imag,
                                const int*   __restrict__ steps_p,
                                float4* __restrict__ out)
{
    // Grid is exactly <<<1,1>>>: no thread guard; loads issue immediately.
    const float wF   = __ldg(omega_mean);
    const float Kc   = __ldg(coupling);
    const float dltF = __ldg(delta);
    const float zr0  = __ldg(Z_real);
    const float zi0  = __ldg(Z_imag);
    const int   n    = __ldg(steps_p);

    const float KhF  = 0.5f * Kc;
    const float c    = DT * wF;
    const float csq  = c * c;
    const float g    = DT * KhF;
    const float lin  = DT * (KhF - dltF);     // b0 - 1
    const float b0   = 1.0f + lin;

    const float s0 = __fmaf_rn(zr0, zr0, zi0 * zi0);

    const float discF = __fmaf_rn(-c, c, 1.0f);
    bool ok = (n >= 20000) && (s0 > 1e-30f) && (g > 0.0f) &&
              (discF > 1e-4f) && (fabsf(c) < 0.0499f); // series validity

    // ---- y = c / sqrt(1-c^2) to ~3e-13 rel: rsqrtf seed + 1 double Newton ----
    double phiInf = 0.0;
    float  b_inf = 0.0f, s_inf = 0.0f;
    if (ok) {
        const double cd   = (double)c;
        const double disc = fma(-cd, cd, 1.0);
        double r = (double)rsqrtf(discF);                 // ~2^-22 rel seed
        r = r * fma(-0.5 * disc, r * r, 1.5);             // 1 Newton -> ~3e-13
        const double y  = cd * r;
        const double y2 = y * y;
        double p = -1.0 / 7.0;
        p = fma(p, y2,  1.0 / 5.0);
        p = fma(p, y2, -1.0 / 3.0);
        p = fma(p, y2,  1.0);
        phiInf = -(y * p);                                // -atan(y), err<3e-13

        b_inf = (float)(disc * r);                        // sqrt(1-c^2)
        // b0 - b_inf = lin + c^2/(1+b_inf): cancellation-free
        const float diff = lin + __fdividef(csq, 1.0f + b_inf);
        s_inf = __fdividef(diff, g);
        if (s_inf > 1e-12f) {
            const float rho = 1.0f - 2.0f * g * s_inf * b_inf;
            ok = (rho > 0.0f) && (rho < 1.0f) &&
                 ((float)n * (1.0f - rho) > 60.0f);       // rho^n -> 0
        } else ok = false;
    }

    const float A = __fmaf_rn(b0, b0, csq);
    const float B = 2.0f * b0 * g;
    const float C = g * g;

    float r1L = 0.0f, r2 = 0.0f, u0 = 0.0f, xq = 0.0f, xr = 0.0f;
    if (ok) {
        const float L1c = __fmaf_rn(b0, b_inf, csq);      // b0*b_inf + c^2
        r1L = __fdividef(L1c, g * b_inf);
        r2  = __fdividef(B, C) - s_inf;
        const float L1s0 = __fmaf_rn(-g * b_inf, s0, L1c);
        u0  = __fdividef(c * g * (s0 - s_inf), L1s0);
        xq  = __fdividef(s0 - s_inf, r1L - s0);
        xr  = __fdividef(s0 - s_inf, r2 - s0);
        ok = (fabsf(u0) < 0.02f) && (fabsf(xq) < 0.1f) && (fabsf(xr) < 0.1f) &&
             (s0 < 0.5f * r1L) && (s0 < 0.5f * r2) && (L1s0 > 1e-10f);
    }

    float4 res;

    if (ok) {
        // ---- main rational integral: exact partial fractions (float) ----
        const float K0  = __fdividef(-c, b_inf * C);
        const float dQR = r1L - r2;
        const float P   = __fdividef(-1.0f, r1L * r2);
        const float Q   = __fdividef( 1.0f, r1L * dQR);
        const float Rc  = __fdividef( 1.0f, r2  * dQR);

        float sumPsi = K0 * ( P  * __logf(__fdividef(s_inf, s0))
                            - Q  * log1p_small_f(xq)
                            + Rc * log1p_small_f(xr) );

        // ---- modified-field correction: (1/2)∫ psi D'/D ds, 3-pt Gauss ----
        {
            const float mid  = 0.5f * (s0 + s_inf);
            const float half = 0.5f * (s_inf - s0);
            const float nd   = 0.77459666924f * half;
            const float sg[3] = { mid - nd, mid, mid + nd };
            const float wg[3] = { 5.0f / 9.0f, 8.0f / 9.0f, 5.0f / 9.0f };
            const float A1  = A - 1.0f;
            const float L1c = __fmaf_rn(b0, b_inf, csq);
            float acc = 0.0f;
            #pragma unroll
            for (int i = 0; i < 3; ++i) {
                const float s  = sg[i];
                const float L1 = __fmaf_rn(-g * b_inf, s, L1c);
                const float L2 = __fmaf_rn(C, s, C * s_inf - B);   // C (s - r2)
                const float Dp = __fmaf_rn(s, __fmaf_rn(3.0f * C, s, -2.0f * B), A1);
                acc += wg[i] * __fdividef(Dp, s * L1 * L2);
            }
            sumPsi += (-0.5f * c * g) * acc * half;
        }

        // ---- EM endpoint ----
        sumPsi -= 0.5f * atan_small_f(u0);

        // ---- total phase (double for the big product) + mod 2*pi ----
        float theta0F;
        if (zi0 == 0.0f && zr0 > 0.0f) theta0F = 0.0f;
        else                           theta0F = atan2f(zi0, zr0);
        const double theta = (double)theta0F + (double)n * phiInf + (double)sumPsi;

        const double TWO_PI_HI = 6.283185307179586;
        const double TWO_PI_LO = 2.4492935982947064e-16;
        const double k = rint(theta * 0.15915494309189535);
        const double r = fma(-k, TWO_PI_LO, fma(-k, TWO_PI_HI, theta));

        const float Rf   = sqrtf(s_inf);
        const float PsiF = (float)r;          // in (-pi, pi] == atan2 range
        float sa, ca;
        __sincosf(PsiF, &sa, &ca);
        res.x = Rf;
        res.y = PsiF;
        res.z = Rf * ca;
        res.w = Rf * sa;
    } else {
        // ---- exact fallback: full float iteration of the original map ----
        float s = s0, zr = zr0, zi = zi0;
        #pragma unroll 16
        for (int i = 0; i < n; ++i) {
            const float b = __fmaf_rn(-g, s, b0);
            const float m = __fmaf_rn(b, b, csq);
            const float czr = c * zr;
            const float czi = c * zi;
            const float nzr = __fmaf_rn(b, zr, czi);
            const float nzi = __fmaf_rn(b, zi, -czr);
            s  = s * m;
            zr = nzr;
            zi = nzi;
        }
        res.x = sqrtf(__fmaf_rn(zr, zr, zi * zi));
        res.y = atan2f(zi, zr);
        res.z = zr;
        res.w = zi;
    }

    *out = res;   // single STG.128
}

extern "C" void kernel_launch(void* const* d_in, const int* in_sizes, int n_in,
                              void* d_out, int out_size)
{
    (void)in_sizes; (void)n_in; (void)out_size;
    const float* omega_mean = (const float*)d_in[0];
    const float* coupling   = (const float*)d_in[1];
    const float* delta      = (const float*)d_in[2];
    const float* Z_real     = (const float*)d_in[3];
    const float* Z_imag     = (const float*)d_in[4];
    const int*   steps      = (const int*)  d_in[5];
    float4* out = (float4*)d_out;

    kuramoto_kernel<<<1, 1>>>(omega_mean, coupling, delta, Z_real, Z_imag, steps, out);
}

// round 16
// speedup vs baseline: 1.0385x; 1.0385x over previous
#include <cuda_runtime.h>
#include <cuda_bf16.h>

// KuramotoDaidoMeanField — closed-form evaluation (no iteration), TERMINAL.
// Session-consensus binary: R8 arithmetic (rel_err canary 4.323573e-05),
// guard-free entry, 31 regs. Eight equivalent submissions sampled the harness
// single-launch floor (dur 6.62-6.91 us); no .cu edit moves it further.
//
// Method summary (derivation in R5):
//   Euler map: z' = (b - i c) z, b = b0 - g s, s = |z|^2
//   Radial map s' = s*m(s), m(s) = A - B s + C s^2 factors EXACTLY as
//   m(s)-1 = C (s - s_inf)(s - r2), s_inf = (b0 - sqrt(1-c^2))/g.
//   Total phase  = theta0 + N*phi_inf + Sum_j [phi(s_j) - phi_inf], where the
//   trajectory sum is evaluated in closed form via Abel/Euler-Maclaurin:
//     exact-partial-fraction rational integral (one log + two log1p series)
//     + (1/2)∫ psi D'/D ds (3-pt Gauss) + psi(s0)/2 endpoint.
//   Magnitude = sqrt(s_inf)  (rho^N -> 0 enforced by guard).
//   FP64 only for n*phi_inf (rsqrtf seed + 1 double Newton for c/sqrt(1-c^2))
//   and the mod-2pi fold; all else float (__fdividef/__logf).
//   Non-conforming inputs -> exact full-iteration fallback.

#define DT 0.01f

__device__ __forceinline__ float atan_small_f(float y)
{
    const float y2 = y * y;
    float p = -1.0f / 7.0f;
    p = __fmaf_rn(p, y2,  1.0f / 5.0f);
    p = __fmaf_rn(p, y2, -1.0f / 3.0f);
    p = __fmaf_rn(p, y2,  1.0f);
    return y * p;
}

__device__ __forceinline__ float log1p_small_f(float x)
{
    float p =  1.0f / 5.0f;
    p = __fmaf_rn(p, x, -1.0f / 4.0f);
    p = __fmaf_rn(p, x,  1.0f / 3.0f);
    p = __fmaf_rn(p, x, -1.0f / 2.0f);
    return x * __fmaf_rn(p, x, 1.0f);
}

__global__ void kuramoto_kernel(const float* __restrict__ omega_mean,
                                const float* __restrict__ coupling,
                                const float* __restrict__ delta,
                                const float* __restrict__ Z_real,
                                const float* __restrict__ Z_imag,
                                const int*   __restrict__ steps_p,
                                float4* __restrict__ out)
{
    // Grid is exactly <<<1,1>>>: loads issue at instruction 0 (MLP=6).
    const float wF   = __ldg(omega_mean);
    const float Kc   = __ldg(coupling);
    const float dltF = __ldg(delta);
    const float zr0  = __ldg(Z_real);
    const float zi0  = __ldg(Z_imag);
    const int   n    = __ldg(steps_p);

    const float KhF  = 0.5f * Kc;
    const float c    = DT * wF;
    const float csq  = c * c;
    const float g    = DT * KhF;
    const float lin  = DT * (KhF - dltF);     // b0 - 1
    const float b0   = 1.0f + lin;

    const float s0 = __fmaf_rn(zr0, zr0, zi0 * zi0);

    const float discF = __fmaf_rn(-c, c, 1.0f);
    bool ok = (n >= 20000) && (s0 > 1e-30f) && (g > 0.0f) &&
              (discF > 1e-4f) && (fabsf(c) < 0.0499f); // series validity

    // ---- y = c / sqrt(1-c^2) to ~3e-13 rel: rsqrtf seed + 1 double Newton ----
    double phiInf = 0.0;
    float  b_inf = 0.0f, s_inf = 0.0f;
    if (ok) {
        const double cd   = (double)c;
        const double disc = fma(-cd, cd, 1.0);
        double r = (double)rsqrtf(discF);                 // ~2^-22 rel seed
        r = r * fma(-0.5 * disc, r * r, 1.5);             // 1 Newton -> ~3e-13
        const double y  = cd * r;
        const double y2 = y * y;
        double p = -1.0 / 7.0;
        p = fma(p, y2,  1.0 / 5.0);
        p = fma(p, y2, -1.0 / 3.0);
        p = fma(p, y2,  1.0);
        phiInf = -(y * p);                                // -atan(y), err<3e-13

        b_inf = (float)(disc * r);                        // sqrt(1-c^2)
        // b0 - b_inf = lin + c^2/(1+b_inf): cancellation-free
        const float diff = lin + __fdividef(csq, 1.0f + b_inf);
        s_inf = __fdividef(diff, g);
        if (s_inf > 1e-12f) {
            const float rho = 1.0f - 2.0f * g * s_inf * b_inf;
            ok = (rho > 0.0f) && (rho < 1.0f) &&
                 ((float)n * (1.0f - rho) > 60.0f);       // rho^n -> 0
        } else ok = false;
    }

    const float A = __fmaf_rn(b0, b0, csq);
    const float B = 2.0f * b0 * g;
    const float C = g * g;

    float r1L = 0.0f, r2 = 0.0f, u0 = 0.0f, xq = 0.0f, xr = 0.0f;
    if (ok) {
        const float L1c = __fmaf_rn(b0, b_inf, csq);      // b0*b_inf + c^2
        r1L = __fdividef(L1c, g * b_inf);
        r2  = __fdividef(B, C) - s_inf;
        const float L1s0 = __fmaf_rn(-g * b_inf, s0, L1c);
        u0  = __fdividef(c * g * (s0 - s_inf), L1s0);
        xq  = __fdividef(s0 - s_inf, r1L - s0);
        xr  = __fdividef(s0 - s_inf, r2 - s0);
        ok = (fabsf(u0) < 0.02f) && (fabsf(xq) < 0.1f) && (fabsf(xr) < 0.1f) &&
             (s0 < 0.5f * r1L) && (s0 < 0.5f * r2) && (L1s0 > 1e-10f);
    }

    float4 res;

    if (ok) {
        // ---- main rational integral: exact partial fractions (float) ----
        const float K0  = __fdividef(-c, b_inf * C);
        const float dQR = r1L - r2;
        const float P   = __fdividef(-1.0f, r1L * r2);
        const float Q   = __fdividef( 1.0f, r1L * dQR);
        const float Rc  = __fdividef( 1.0f, r2  * dQR);

        float sumPsi = K0 * ( P  * __logf(__fdividef(s_inf, s0))
                            - Q  * log1p_small_f(xq)
                            + Rc * log1p_small_f(xr) );

        // ---- modified-field correction: (1/2)∫ psi D'/D ds, 3-pt Gauss ----
        {
            const float mid  = 0.5f * (s0 + s_inf);
            const float half = 0.5f * (s_inf - s0);
            const float nd   = 0.77459666924f * half;
            const float sg[3] = { mid - nd, mid, mid + nd };
            const float wg[3] = { 5.0f / 9.0f, 8.0f / 9.0f, 5.0f / 9.0f };
            const float A1  = A - 1.0f;
            const float L1c = __fmaf_rn(b0, b_inf, csq);
            float acc = 0.0f;
            #pragma unroll
            for (int i = 0; i < 3; ++i) {
                const float s  = sg[i];
                const float L1 = __fmaf_rn(-g * b_inf, s, L1c);
                const float L2 = __fmaf_rn(C, s, C * s_inf - B);   // C (s - r2)
                const float Dp = __fmaf_rn(s, __fmaf_rn(3.0f * C, s, -2.0f * B), A1);
                acc += wg[i] * __fdividef(Dp, s * L1 * L2);
            }
            sumPsi += (-0.5f * c * g) * acc * half;
        }

        // ---- EM endpoint ----
        sumPsi -= 0.5f * atan_small_f(u0);

        // ---- total phase (double for the big product) + mod 2*pi ----
        float theta0F;
        if (zi0 == 0.0f && zr0 > 0.0f) theta0F = 0.0f;
        else                           theta0F = atan2f(zi0, zr0);
        const double theta = (double)theta0F + (double)n * phiInf + (double)sumPsi;

        const double TWO_PI_HI = 6.283185307179586;
        const double TWO_PI_LO = 2.4492935982947064e-16;
        const double k = rint(theta * 0.15915494309189535);
        const double r = fma(-k, TWO_PI_LO, fma(-k, TWO_PI_HI, theta));

        const float Rf   = sqrtf(s_inf);
        const float PsiF = (float)r;          // in (-pi, pi] == atan2 range
        float sa, ca;
        __sincosf(PsiF, &sa, &ca);
        res.x = Rf;
        res.y = PsiF;
        res.z = Rf * ca;
        res.w = Rf * sa;
    } else {
        // ---- exact fallback: full float iteration of the original map ----
        float s = s0, zr = zr0, zi = zi0;
        #pragma unroll 16
        for (int i = 0; i < n; ++i) {
            const float b = __fmaf_rn(-g, s, b0);
            const float m = __fmaf_rn(b, b, csq);
            const float czr = c * zr;
            const float czi = c * zi;
            const float nzr = __fmaf_rn(b, zr, czi);
            const float nzi = __fmaf_rn(b, zi, -czr);
            s  = s * m;
            zr = nzr;
            zi = nzi;
        }
        res.x = sqrtf(__fmaf_rn(zr, zr, zi * zi));
        res.y = atan2f(zi, zr);
        res.z = zr;
        res.w = zi;
    }

    *out = res;   // single STG.128
}

extern "C" void kernel_launch(void* const* d_in, const int* in_sizes, int n_in,
                              void* d_out, int out_size)
{
    (void)in_sizes; (void)n_in; (void)out_size;
    const float* omega_mean = (const float*)d_in[0];
    const float* coupling   = (const float*)d_in[1];
    const float* delta      = (const float*)d_in[2];
    const float* Z_real     = (const float*)d_in[3];
    const float* Z_imag     = (const float*)d_in[4];
    const int*   steps      = (const int*)  d_in[5];
    float4* out = (float4*)d_out;

    kuramoto_kernel<<<1, 1>>>(omega_mean, coupling, delta, Z_real, Z_imag, steps, out);
}

// round 17
// speedup vs baseline: 1.0435x; 1.0048x over previous
#include <cuda_runtime.h>
#include <cuda_bf16.h>

// KuramotoDaidoMeanField — closed-form evaluation (no iteration), TERMINAL.
// Session-consensus binary (identical to R16): R8 arithmetic (rel_err canary
// 4.323573e-05), guard-free entry, 31 regs. Nine equivalent submissions
// sample the harness single-launch floor (dur 6.62-6.91 us); resubmitted
// unchanged — any further edit has zero or negative expected value.
//
// Method summary (derivation in R5):
//   Euler map: z' = (b - i c) z, b = b0 - g s, s = |z|^2
//   Radial map s' = s*m(s), m(s) = A - B s + C s^2 factors EXACTLY as
//   m(s)-1 = C (s - s_inf)(s - r2), s_inf = (b0 - sqrt(1-c^2))/g.
//   Total phase  = theta0 + N*phi_inf + Sum_j [phi(s_j) - phi_inf], where the
//   trajectory sum is evaluated in closed form via Abel/Euler-Maclaurin:
//     exact-partial-fraction rational integral (one log + two log1p series)
//     + (1/2)∫ psi D'/D ds (3-pt Gauss) + psi(s0)/2 endpoint.
//   Magnitude = sqrt(s_inf)  (rho^N -> 0 enforced by guard).
//   FP64 only for n*phi_inf (rsqrtf seed + 1 double Newton for c/sqrt(1-c^2))
//   and the mod-2pi fold; all else float (__fdividef/__logf).
//   Non-conforming inputs -> exact full-iteration fallback.

#define DT 0.01f

__device__ __forceinline__ float atan_small_f(float y)
{
    const float y2 = y * y;
    float p = -1.0f / 7.0f;
    p = __fmaf_rn(p, y2,  1.0f / 5.0f);
    p = __fmaf_rn(p, y2, -1.0f / 3.0f);
    p = __fmaf_rn(p, y2,  1.0f);
    return y * p;
}

__device__ __forceinline__ float log1p_small_f(float x)
{
    float p =  1.0f / 5.0f;
    p = __fmaf_rn(p, x, -1.0f / 4.0f);
    p = __fmaf_rn(p, x,  1.0f / 3.0f);
    p = __fmaf_rn(p, x, -1.0f / 2.0f);
    return x * __fmaf_rn(p, x, 1.0f);
}

__global__ void kuramoto_kernel(const float* __restrict__ omega_mean,
                                const float* __restrict__ coupling,
                                const float* __restrict__ delta,
                                const float* __restrict__ Z_real,
                                const float* __restrict__ Z_imag,
                                const int*   __restrict__ steps_p,
                                float4* __restrict__ out)
{
    // Grid is exactly <<<1,1>>>: loads issue at instruction 0 (MLP=6).
    const float wF   = __ldg(omega_mean);
    const float Kc   = __ldg(coupling);
    const float dltF = __ldg(delta);
    const float zr0  = __ldg(Z_real);
    const float zi0  = __ldg(Z_imag);
    const int   n    = __ldg(steps_p);

    const float KhF  = 0.5f * Kc;
    const float c    = DT * wF;
    const float csq  = c * c;
    const float g    = DT * KhF;
    const float lin  = DT * (KhF - dltF);     // b0 - 1
    const float b0   = 1.0f + lin;

    const float s0 = __fmaf_rn(zr0, zr0, zi0 * zi0);

    const float discF = __fmaf_rn(-c, c, 1.0f);
    bool ok = (n >= 20000) && (s0 > 1e-30f) && (g > 0.0f) &&
              (discF > 1e-4f) && (fabsf(c) < 0.0499f); // series validity

    // ---- y = c / sqrt(1-c^2) to ~3e-13 rel: rsqrtf seed + 1 double Newton ----
    double phiInf = 0.0;
    float  b_inf = 0.0f, s_inf = 0.0f;
    if (ok) {
        const double cd   = (double)c;
        const double disc = fma(-cd, cd, 1.0);
        double r = (double)rsqrtf(discF);                 // ~2^-22 rel seed
        r = r * fma(-0.5 * disc, r * r, 1.5);             // 1 Newton -> ~3e-13
        const double y  = cd * r;
        const double y2 = y * y;
        double p = -1.0 / 7.0;
        p = fma(p, y2,  1.0 / 5.0);
        p = fma(p, y2, -1.0 / 3.0);
        p = fma(p, y2,  1.0);
        phiInf = -(y * p);                                // -atan(y), err<3e-13

        b_inf = (float)(disc * r);                        // sqrt(1-c^2)
        // b0 - b_inf = lin + c^2/(1+b_inf): cancellation-free
        const float diff = lin + __fdividef(csq, 1.0f + b_inf);
        s_inf = __fdividef(diff, g);
        if (s_inf > 1e-12f) {
            const float rho = 1.0f - 2.0f * g * s_inf * b_inf;
            ok = (rho > 0.0f) && (rho < 1.0f) &&
                 ((float)n * (1.0f - rho) > 60.0f);       // rho^n -> 0
        } else ok = false;
    }

    const float A = __fmaf_rn(b0, b0, csq);
    const float B = 2.0f * b0 * g;
    const float C = g * g;

    float r1L = 0.0f, r2 = 0.0f, u0 = 0.0f, xq = 0.0f, xr = 0.0f;
    if (ok) {
        const float L1c = __fmaf_rn(b0, b_inf, csq);      // b0*b_inf + c^2
        r1L = __fdividef(L1c, g * b_inf);
        r2  = __fdividef(B, C) - s_inf;
        const float L1s0 = __fmaf_rn(-g * b_inf, s0, L1c);
        u0  = __fdividef(c * g * (s0 - s_inf), L1s0);
        xq  = __fdividef(s0 - s_inf, r1L - s0);
        xr  = __fdividef(s0 - s_inf, r2 - s0);
        ok = (fabsf(u0) < 0.02f) && (fabsf(xq) < 0.1f) && (fabsf(xr) < 0.1f) &&
             (s0 < 0.5f * r1L) && (s0 < 0.5f * r2) && (L1s0 > 1e-10f);
    }

    float4 res;

    if (ok) {
        // ---- main rational integral: exact partial fractions (float) ----
        const float K0  = __fdividef(-c, b_inf * C);
        const float dQR = r1L - r2;
        const float P   = __fdividef(-1.0f, r1L * r2);
        const float Q   = __fdividef( 1.0f, r1L * dQR);
        const float Rc  = __fdividef( 1.0f, r2  * dQR);

        float sumPsi = K0 * ( P  * __logf(__fdividef(s_inf, s0))
                            - Q  * log1p_small_f(xq)
                            + Rc * log1p_small_f(xr) );

        // ---- modified-field correction: (1/2)∫ psi D'/D ds, 3-pt Gauss ----
        {
            const float mid  = 0.5f * (s0 + s_inf);
            const float half = 0.5f * (s_inf - s0);
            const float nd   = 0.77459666924f * half;
            const float sg[3] = { mid - nd, mid, mid + nd };
            const float wg[3] = { 5.0f / 9.0f, 8.0f / 9.0f, 5.0f / 9.0f };
            const float A1  = A - 1.0f;
            const float L1c = __fmaf_rn(b0, b_inf, csq);
            float acc = 0.0f;
            #pragma unroll
            for (int i = 0; i < 3; ++i) {
                const float s  = sg[i];
                const float L1 = __fmaf_rn(-g * b_inf, s, L1c);
                const float L2 = __fmaf_rn(C, s, C * s_inf - B);   // C (s - r2)
                const float Dp = __fmaf_rn(s, __fmaf_rn(3.0f * C, s, -2.0f * B), A1);
                acc += wg[i] * __fdividef(Dp, s * L1 * L2);
            }
            sumPsi += (-0.5f * c * g) * acc * half;
        }

        // ---- EM endpoint ----
        sumPsi -= 0.5f * atan_small_f(u0);

        // ---- total phase (double for the big product) + mod 2*pi ----
        float theta0F;
        if (zi0 == 0.0f && zr0 > 0.0f) theta0F = 0.0f;
        else                           theta0F = atan2f(zi0, zr0);
        const double theta = (double)theta0F + (double)n * phiInf + (double)sumPsi;

        const double TWO_PI_HI = 6.283185307179586;
        const double TWO_PI_LO = 2.4492935982947064e-16;
        const double k = rint(theta * 0.15915494309189535);
        const double r = fma(-k, TWO_PI_LO, fma(-k, TWO_PI_HI, theta));

        const float Rf   = sqrtf(s_inf);
        const float PsiF = (float)r;          // in (-pi, pi] == atan2 range
        float sa, ca;
        __sincosf(PsiF, &sa, &ca);
        res.x = Rf;
        res.y = PsiF;
        res.z = Rf * ca;
        res.w = Rf * sa;
    } else {
        // ---- exact fallback: full float iteration of the original map ----
        float s = s0, zr = zr0, zi = zi0;
        #pragma unroll 16
        for (int i = 0; i < n; ++i) {
            const float b = __fmaf_rn(-g, s, b0);
            const float m = __fmaf_rn(b, b, csq);
            const float czr = c * zr;
            const float czi = c * zi;
            const float nzr = __fmaf_rn(b, zr, czi);
            const float nzi = __fmaf_rn(b, zi, -czr);
            s  = s * m;
            zr = nzr;
            zi = nzi;
        }
        res.x = sqrtf(__fmaf_rn(zr, zr, zi * zi));
        res.y = atan2f(zi, zr);
        res.z = zr;
        res.w = zi;
    }

    *out = res;   // single STG.128
}

extern "C" void kernel_launch(void* const* d_in, const int* in_sizes, int n_in,
                              void* d_out, int out_size)
{
    (void)in_sizes; (void)n_in; (void)out_size;
    const float* omega_mean = (const float*)d_in[0];
    const float* coupling   = (const float*)d_in[1];
    const float* delta      = (const float*)d_in[2];
    const float* Z_real     = (const float*)d_in[3];
    const float* Z_imag     = (const float*)d_in[4];
    const int*   steps      = (const int*)  d_in[5];
    float4* out = (float4*)d_out;

    kuramoto_kernel<<<1, 1>>>(omega_mean, coupling, delta, Z_real, Z_imag, steps, out);
}